// round 14
// baseline (speedup 1.0000x reference)
#include <cuda_runtime.h>
#include <cuda_fp16.h>
#include <cstdint>

// GraphAttentionLayer: N=12288, IN_F=256, OUT_F=128, slope=0.2
// out = [h_prime (N x 128) | attention (N x N)] fp32.
//
//  k_pre   : h_t = h @ W in regs -> htT fp16 (k-permuted) + exp tables;
//            block 0 zeroes g_done counters.
//  k_fused : 96 tile-groups x (16 bits-blocks + 3 main-blocks).
//            bits role: adj -> bitmask + folded denominators, then
//            release g_done[tile]. main role (tile (q+8)%96): spins on
//            g_done, then R13 pipeline (kk-granular fragment-gen inside
//            MMA sweep, cp.async double-buffer, streaming attn stores).
//            Deadlock-free: 288 main blocks < 296 guaranteed resident slots.
//  k_red   : sum 3 partials -> h_prime.

#define KN    12288
#define INF_  256
#define OUTF  128
#define NWORDS (KN / 32)     // 384
#define CH    128            // K-chunk
#define NSPLIT 3
#define NCL   (KN / CH / NSPLIT)   // 32 chunks per split
#define JSPAN (KN / NSPLIT)        // 4096
#define NTILE (KN / 128)           // 96
#define LAG   8

__device__ __half g_htT[(size_t)OUTF * KN];   // k-permuted layout
__device__ __align__(16) float g_Es[KN], g_Es2[KN], g_Etgt[KN], g_Etgt2[KN];
__device__ float g_A[KN], g_B[KN];
__device__ __align__(16) uint32_t g_bits[(size_t)KN * NWORDS];
__device__ float g_part[(size_t)NSPLIT * KN * OUTF];
__device__ int g_done[NTILE];

// ---------------- helpers ----------------
__device__ __forceinline__ uint32_t smem_u32(const void* p) {
    uint32_t a;
    asm("{ .reg .u64 t; cvta.to.shared.u64 t, %1; cvt.u32.u64 %0, t; }" : "=r"(a) : "l"(p));
    return a;
}
__device__ __forceinline__ uint32_t packh2(float p0, float p1) {
    uint32_t r;
    asm("cvt.rn.f16x2.f32 %0, %1, %2;" : "=r"(r) : "f"(p1), "f"(p0));
    return r;
}
__device__ __forceinline__ void stcs4(float* p, float a, float b, float c, float d) {
    asm volatile("st.global.cs.v4.f32 [%0], {%1, %2, %3, %4};"
                 :: "l"(p), "f"(a), "f"(b), "f"(c), "f"(d));
}

#define MMA16816(d, a0, a1, a2, a3, b0, b1) \
    asm volatile( \
        "mma.sync.aligned.m16n8k16.row.col.f32.f16.f16.f32 " \
        "{%0,%1,%2,%3}, {%4,%5,%6,%7}, {%8,%9}, {%0,%1,%2,%3};" \
        : "+f"((d).x), "+f"((d).y), "+f"((d).z), "+f"((d).w) \
        : "r"(a0), "r"(a1), "r"(a2), "r"(a3), "r"(b0), "r"(b1))

#define LDMX4(r0, r1, r2, r3, ad) \
    asm volatile("ldmatrix.sync.aligned.m8n8.x4.shared.b16 {%0,%1,%2,%3}, [%4];" \
                 : "=r"(r0), "=r"(r1), "=r"(r2), "=r"(r3) : "r"(ad))

#define CP16(dst, src) \
    asm volatile("cp.async.cg.shared.global [%0], [%1], 16;" :: "r"(dst), "l"(src) : "memory")
#define CP_COMMIT() asm volatile("cp.async.commit_group;" ::: "memory")
#define CP_WAIT1()  asm volatile("cp.async.wait_group 1;" ::: "memory")
#define CP_WAIT0()  asm volatile("cp.async.wait_group 0;" ::: "memory")

// ---------------- K1: fused h@W -> permuted htT fp16 + exp tables -----------
__global__ void __launch_bounds__(256) k_pre(const float* __restrict__ h,
                                             const float* __restrict__ W,
                                             const float* __restrict__ a) {
    __shared__ float h_s[8 * INF_];
    __shared__ float red[8][8];
    int t = threadIdx.x;
    int r0 = blockIdx.x * 8;
    if (blockIdx.x == 0 && t < NTILE) g_done[t] = 0;   // reset gates each replay
    for (int idx = t; idx < 8 * INF_; idx += 256)
        h_s[idx] = h[(size_t)r0 * INF_ + idx];
    __syncthreads();
    int c  = t & 127;
    int rg = t >> 7;
    float acc[4] = {0.f, 0.f, 0.f, 0.f};
    for (int k = 0; k < INF_; k++) {
        float w = W[k * OUTF + c];
#pragma unroll
        for (int rr = 0; rr < 4; rr++)
            acc[rr] = fmaf(h_s[(rg * 4 + rr) * INF_ + k], w, acc[rr]);
    }
    // permuted store: 4 consecutive j (= one t-group) -> k-pairs {2T, 2T+8}
    {
        int jj  = r0 + rg * 4;
        int grp = jj & ~15;
        int T   = (jj & 15) >> 2;
        __half* dst = g_htT + (size_t)c * KN + grp;
        *(uint32_t*)(dst + 2 * T)     = packh2(acc[0], acc[1]);
        *(uint32_t*)(dst + 2 * T + 8) = packh2(acc[2], acc[3]);
    }

    float av = a[c], av2 = a[OUTF + c];
    float s[8];
#pragma unroll
    for (int rr = 0; rr < 4; rr++) {
        s[rr * 2]     = acc[rr] * av;
        s[rr * 2 + 1] = acc[rr] * av2;
    }
#pragma unroll
    for (int o = 16; o > 0; o >>= 1)
#pragma unroll
        for (int i = 0; i < 8; i++)
            s[i] += __shfl_down_sync(0xFFFFFFFFu, s[i], o);
    int w = t >> 5, l = t & 31;
    if (l == 0)
#pragma unroll
        for (int i = 0; i < 8; i++) red[w][i] = s[i];
    __syncthreads();
    if (t < 16) {
        int rho = t >> 1, which = t & 1;
        int rg2 = rho >> 2, rr = rho & 3;
        float v = red[rg2 * 4 + 0][rr * 2 + which] + red[rg2 * 4 + 1][rr * 2 + which]
                + red[rg2 * 4 + 2][rr * 2 + which] + red[rg2 * 4 + 3][rr * 2 + which];
        int r = r0 + rho;
        if (which == 0) { g_Es[r]   = expf(v); g_Es2[r]   = expf(0.2f * v); }
        else            { g_Etgt[r] = expf(v); g_Etgt2[r] = expf(0.2f * v); }
    }
}

// ---------------- K2: fused bits + main --------------------------------
#define ROWSTRIDE 272
#define VERBYTES  (128 * ROWSTRIDE)   // 34816
#define SMEM_MAIN (2 * VERBYTES)      // 69632

#define GEN_KK(JLOC, WORD0, WORD1, DST) do {                                  \
    const int j_ = jbase + (JLOC) + 4 * tq;                                   \
    float4 e1 = *(const float4*)(g_Etgt  + j_);                               \
    float4 e2 = *(const float4*)(g_Etgt2 + j_);                               \
    const uint32_t nib0 = (WORD0) >> (4 * tq);                                \
    const uint32_t nib1 = (WORD1) >> (4 * tq);                                \
    float p00 = nib0 & 1 ? fmaxf(aA0 * e1.x, bB0 * e2.x) : 0.f;               \
    float p01 = nib0 & 2 ? fmaxf(aA0 * e1.y, bB0 * e2.y) : 0.f;               \
    float p02 = nib0 & 4 ? fmaxf(aA0 * e1.z, bB0 * e2.z) : 0.f;               \
    float p03 = nib0 & 8 ? fmaxf(aA0 * e1.w, bB0 * e2.w) : 0.f;               \
    float p10 = nib1 & 1 ? fmaxf(aA1 * e1.x, bB1 * e2.x) : 0.f;               \
    float p11 = nib1 & 2 ? fmaxf(aA1 * e1.y, bB1 * e2.y) : 0.f;               \
    float p12 = nib1 & 4 ? fmaxf(aA1 * e1.z, bB1 * e2.z) : 0.f;               \
    float p13 = nib1 & 8 ? fmaxf(aA1 * e1.w, bB1 * e2.w) : 0.f;               \
    stcs4(attn0 + j_, p00, p01, p02, p03);                                    \
    stcs4(attn1 + j_, p10, p11, p12, p13);                                    \
    (DST)[0] = packh2(p00, p01);                                              \
    (DST)[1] = packh2(p10, p11);                                              \
    (DST)[2] = packh2(p02, p03);                                              \
    (DST)[3] = packh2(p12, p13);                                              \
} while (0)

__global__ void __launch_bounds__(256, 2) k_fused(const int* __restrict__ adj,
                                                  float* __restrict__ out) {
    const int q    = blockIdx.x / 19;
    const int rsub = blockIdx.x - q * 19;
    const int t = threadIdx.x;

    if (rsub < 16) {
        // ================= bits role: 8 rows of tile q =================
        int l = t & 31;
        int r = q * 128 + rsub * 8 + (t >> 5);
        float Es = g_Es[r], Es2 = g_Es2[r];
        const int4* __restrict__ arow = (const int4*)(adj + (size_t)r * KN);
        uint32_t* __restrict__ brow = g_bits + (size_t)r * NWORDS;
        const int sh = (l & 7) * 4;
        float ls0 = 0.f, ls1 = 0.f, ls2 = 0.f, ls3 = 0.f;

#pragma unroll 8
        for (int it = 0; it < KN / 128; it++) {
            int j = it * 128 + l * 4;
            int4 m = __ldcs(arow + it * 32 + l);
            float4 e1 = *(const float4*)(g_Etgt + j);
            float4 e2 = *(const float4*)(g_Etgt2 + j);
            uint32_t nib = 0;
            if (m.x) { nib |= 1u; ls0 += fmaxf(Es * e1.x, Es2 * e2.x); }
            if (m.y) { nib |= 2u; ls1 += fmaxf(Es * e1.y, Es2 * e2.y); }
            if (m.z) { nib |= 4u; ls2 += fmaxf(Es * e1.z, Es2 * e2.z); }
            if (m.w) { nib |= 8u; ls3 += fmaxf(Es * e1.w, Es2 * e2.w); }
            uint32_t word = nib << sh;
            word |= __shfl_xor_sync(0xFFFFFFFFu, word, 1);
            word |= __shfl_xor_sync(0xFFFFFFFFu, word, 2);
            word |= __shfl_xor_sync(0xFFFFFFFFu, word, 4);
            if ((l & 7) == 0) brow[it * 4 + (l >> 3)] = word;
        }
        float lsum = (ls0 + ls1) + (ls2 + ls3);
#pragma unroll
        for (int o = 16; o > 0; o >>= 1) lsum += __shfl_down_sync(0xFFFFFFFFu, lsum, o);
        if (l == 0) {
            float inv = 1.0f / lsum;
            g_A[r] = Es * inv;
            g_B[r] = Es2 * inv;
        }
        __threadfence();          // publish rows device-wide
        __syncthreads();
        if (t == 0) atomicAdd(&g_done[q], 1);
        return;
    }

    // ================= main role: tile (q+LAG)%96, third rsub-16 =========
    extern __shared__ char sm[];
    const uint32_t smb = smem_u32(sm);
    const int w  = t >> 5, l = t & 31;
    const int g  = l >> 2, tq = l & 3;
    const int ti = (q + LAG) % NTILE;
    const int js = rsub - 16;
    const int i0 = ti * 128;
    const int jbase = js * JSPAN;
    const int row0 = i0 + w * 16 + g;
    const int row1 = row0 + 8;

    const int cpr = t >> 4;
    const int cpk = t & 15;
    const uint32_t lmrow = ((l >> 4) & 1) * 8 + (l & 7);
    const uint32_t lmoff = lmrow * ROWSTRIDE + ((l >> 3) & 1) * 16;

    float4 acc[16];
#pragma unroll
    for (int i = 0; i < 16; i++) acc[i] = make_float4(0.f, 0.f, 0.f, 0.f);

    // prologue cp.async (htT only — independent of the gate)
#pragma unroll
    for (int i = 0; i < 8; i++) {
        int row = cpr + i * 16;
        CP16(smb + row * ROWSTRIDE + cpk * 16,
             g_htT + (size_t)row * KN + jbase + cpk * 8);
    }
    CP_COMMIT();

    // gate: wait for tile's bits/denominators
    if (t == 0) {
        volatile int* dp = g_done + ti;
        while (*dp != 16) __nanosleep(128);
    }
    __syncthreads();
    __threadfence();

    const float aA0 = g_A[row0], bB0 = g_B[row0];
    const float aA1 = g_A[row1], bB1 = g_B[row1];
    float* __restrict__ attn0 = out + (size_t)KN * OUTF + (size_t)row0 * KN;
    float* __restrict__ attn1 = out + (size_t)KN * OUTF + (size_t)row1 * KN;
    const uint32_t* __restrict__ bw0 = g_bits + (size_t)row0 * NWORDS + js * NCL * 4;
    const uint32_t* __restrict__ bw1 = g_bits + (size_t)row1 * NWORDS + js * NCL * 4;

    uint32_t ahP[2][4];
    {
        const uint32_t x0 = bw0[0], x1 = bw1[0];
        GEN_KK(0, x0, x1, ahP[0]);
    }

    for (int c = 0; c < NCL; c++) {
        const int buf = c & 1;
        const uint4 w0 = *(const uint4*)(bw0 + c * 4);
        const uint4 w1 = *(const uint4*)(bw1 + c * 4);
        const int more = (c + 1 < NCL);
        const uint32_t nx0 = more ? bw0[(c + 1) * 4] : 0u;
        const uint32_t nx1 = more ? bw1[(c + 1) * 4] : 0u;

        if (more) {
            const int jn = jbase + (c + 1) * CH;
            const uint32_t dstb = smb + (buf ^ 1) * VERBYTES;
#pragma unroll
            for (int i = 0; i < 8; i++) {
                int row = cpr + i * 16;
                CP16(dstb + row * ROWSTRIDE + cpk * 16,
                     g_htT + (size_t)row * KN + jn + cpk * 8);
            }
            CP_COMMIT();
            CP_WAIT1();
        } else {
            CP_WAIT0();
        }
        __syncthreads();

        const uint32_t lmb = smb + buf * VERBYTES + lmoff;
        uint32_t b0, b1, b2, b3;
        LDMX4(b0, b1, b2, b3, lmb);
#pragma unroll
        for (int it = 0; it < 64; it++) {
            const int kk = it >> 3, np = it & 7;
            uint32_t n0, n1, n2, n3;
            if (it < 63) {
                const int itn = it + 1;
                LDMX4(n0, n1, n2, n3,
                      lmb + (itn & 7) * (16 * ROWSTRIDE) + (itn >> 3) * 32);
            }
            MMA16816(acc[2 * np],     ahP[kk & 1][0], ahP[kk & 1][1],
                                      ahP[kk & 1][2], ahP[kk & 1][3], b0, b1);
            MMA16816(acc[2 * np + 1], ahP[kk & 1][0], ahP[kk & 1][1],
                                      ahP[kk & 1][2], ahP[kk & 1][3], b2, b3);
            if (np == 2) {
                if (kk < 7) {
                    const uint32_t x0 = ((const uint32_t*)&w0)[(kk + 1) >> 1] >> (((kk + 1) & 1) * 16);
                    const uint32_t x1 = ((const uint32_t*)&w1)[(kk + 1) >> 1] >> (((kk + 1) & 1) * 16);
                    GEN_KK(c * CH + (kk + 1) * 16, x0, x1, ahP[(kk + 1) & 1]);
                } else if (more) {
                    GEN_KK((c + 1) * CH, nx0, nx1, ahP[0]);
                }
            }
            if (it < 63) { b0 = n0; b1 = n1; b2 = n2; b3 = n3; }
        }
        __syncthreads();
    }

    // epilogue: h_prime partial for this j-third
    float* __restrict__ part = g_part + (size_t)js * KN * OUTF;
#pragma unroll
    for (int nt = 0; nt < 16; nt++) {
        int cc = nt * 8 + 2 * tq;
        *(float2*)(part + (size_t)row0 * OUTF + cc) = make_float2(acc[nt].x, acc[nt].y);
        *(float2*)(part + (size_t)row1 * OUTF + cc) = make_float2(acc[nt].z, acc[nt].w);
    }
}

// ---------------- K3: reduce partials ----------------
__global__ void __launch_bounds__(256) k_red(float* __restrict__ out) {
    const size_t SZ = (size_t)KN * OUTF;
    size_t idx = ((size_t)blockIdx.x * 256 + threadIdx.x) * 4;
    float4 a = *(const float4*)(g_part + idx);
    float4 b = *(const float4*)(g_part + SZ + idx);
    float4 c = *(const float4*)(g_part + 2 * SZ + idx);
    *(float4*)(out + idx) = make_float4(a.x + b.x + c.x, a.y + b.y + c.y,
                                        a.z + b.z + c.z, a.w + b.w + c.w);
}

extern "C" void kernel_launch(void* const* d_in, const int* in_sizes, int n_in,
                              void* d_out, int out_size) {
    const float* h   = (const float*)d_in[0];
    const int*   adj = (const int*)d_in[1];
    const float* W   = (const float*)d_in[2];
    const float* a   = (const float*)d_in[3];
    float* out = (float*)d_out;

    cudaFuncSetAttribute(k_fused, cudaFuncAttributeMaxDynamicSharedMemorySize, SMEM_MAIN);

    k_pre<<<KN / 8, 256>>>(h, W, a);
    k_fused<<<NTILE * 19, 256, SMEM_MAIN>>>(adj, out);
    k_red<<<(KN * OUTF) / (256 * 4), 256>>>(out);
}

// round 15
// speedup vs baseline: 2.1770x; 2.1770x over previous
#include <cuda_runtime.h>
#include <cuda_fp16.h>
#include <cstdint>

// GraphAttentionLayer: N=12288, IN_F=256, OUT_F=128, slope=0.2
// out = [h_prime (N x 128) | attention (N x N)] fp32.
//
//  k_pre    : h_t = h @ W in regs (float4-LDS inner loop) -> htT fp16
//             (k-permuted) + exp tables.
//  k_bits   : adj -> packed bitmask + folded denominators (flat, __ldcs).
//  k_main   : grid 288 = 96 row-tiles x 3 j-thirds, 256 thr, 2 blocks/SM;
//             kk-granular software pipeline (R13).
//  k_red    : sum 3 partials -> h_prime.

#define KN    12288
#define INF_  256
#define OUTF  128
#define NWORDS (KN / 32)     // 384
#define CH    128            // K-chunk
#define NSPLIT 3
#define NCL   (KN / CH / NSPLIT)   // 32 chunks per split
#define JSPAN (KN / NSPLIT)        // 4096

__device__ __half g_htT[(size_t)OUTF * KN];   // k-permuted layout
__device__ __align__(16) float g_Es[KN], g_Es2[KN], g_Etgt[KN], g_Etgt2[KN];
__device__ float g_A[KN], g_B[KN];
__device__ __align__(16) uint32_t g_bits[(size_t)KN * NWORDS];
__device__ float g_part[(size_t)NSPLIT * KN * OUTF];

// ---------------- helpers ----------------
__device__ __forceinline__ uint32_t smem_u32(const void* p) {
    uint32_t a;
    asm("{ .reg .u64 t; cvta.to.shared.u64 t, %1; cvt.u32.u64 %0, t; }" : "=r"(a) : "l"(p));
    return a;
}
__device__ __forceinline__ uint32_t packh2(float p0, float p1) {
    uint32_t r;
    asm("cvt.rn.f16x2.f32 %0, %1, %2;" : "=r"(r) : "f"(p1), "f"(p0));
    return r;
}
__device__ __forceinline__ void stcs4(float* p, float a, float b, float c, float d) {
    asm volatile("st.global.cs.v4.f32 [%0], {%1, %2, %3, %4};"
                 :: "l"(p), "f"(a), "f"(b), "f"(c), "f"(d));
}

#define MMA16816(d, a0, a1, a2, a3, b0, b1) \
    asm volatile( \
        "mma.sync.aligned.m16n8k16.row.col.f32.f16.f16.f32 " \
        "{%0,%1,%2,%3}, {%4,%5,%6,%7}, {%8,%9}, {%0,%1,%2,%3};" \
        : "+f"((d).x), "+f"((d).y), "+f"((d).z), "+f"((d).w) \
        : "r"(a0), "r"(a1), "r"(a2), "r"(a3), "r"(b0), "r"(b1))

#define LDMX4(r0, r1, r2, r3, ad) \
    asm volatile("ldmatrix.sync.aligned.m8n8.x4.shared.b16 {%0,%1,%2,%3}, [%4];" \
                 : "=r"(r0), "=r"(r1), "=r"(r2), "=r"(r3) : "r"(ad))

#define CP16(dst, src) \
    asm volatile("cp.async.cg.shared.global [%0], [%1], 16;" :: "r"(dst), "l"(src) : "memory")
#define CP_COMMIT() asm volatile("cp.async.commit_group;" ::: "memory")
#define CP_WAIT1()  asm volatile("cp.async.wait_group 1;" ::: "memory")
#define CP_WAIT0()  asm volatile("cp.async.wait_group 0;" ::: "memory")

// ---------------- K1: fused h@W -> permuted htT fp16 + exp tables -----------
__global__ void __launch_bounds__(256) k_pre(const float* __restrict__ h,
                                             const float* __restrict__ W,
                                             const float* __restrict__ a) {
    __shared__ __align__(16) float h_s[8 * INF_];
    __shared__ float red[8][8];
    int t = threadIdx.x;
    int r0 = blockIdx.x * 8;
    for (int idx = t; idx < 8 * INF_ / 4; idx += 256)
        ((float4*)h_s)[idx] = ((const float4*)(h + (size_t)r0 * INF_))[idx];
    __syncthreads();
    int c  = t & 127;
    int rg = t >> 7;
    const float4* __restrict__ h4 = (const float4*)h_s;
    float acc[4] = {0.f, 0.f, 0.f, 0.f};
#pragma unroll 4
    for (int k = 0; k < INF_; k += 4) {
        float w0 = W[(k + 0) * OUTF + c];
        float w1 = W[(k + 1) * OUTF + c];
        float w2 = W[(k + 2) * OUTF + c];
        float w3 = W[(k + 3) * OUTF + c];
#pragma unroll
        for (int rr = 0; rr < 4; rr++) {
            float4 hv = h4[(rg * 4 + rr) * (INF_ / 4) + (k >> 2)];
            acc[rr] = fmaf(hv.x, w0, acc[rr]);
            acc[rr] = fmaf(hv.y, w1, acc[rr]);
            acc[rr] = fmaf(hv.z, w2, acc[rr]);
            acc[rr] = fmaf(hv.w, w3, acc[rr]);
        }
    }
    // permuted store: 4 consecutive j (= one t-group) -> k-pairs {2T, 2T+8}
    {
        int jj  = r0 + rg * 4;
        int grp = jj & ~15;
        int T   = (jj & 15) >> 2;
        __half* dst = g_htT + (size_t)c * KN + grp;
        *(uint32_t*)(dst + 2 * T)     = packh2(acc[0], acc[1]);
        *(uint32_t*)(dst + 2 * T + 8) = packh2(acc[2], acc[3]);
    }

    float av = a[c], av2 = a[OUTF + c];
    float s[8];
#pragma unroll
    for (int rr = 0; rr < 4; rr++) {
        s[rr * 2]     = acc[rr] * av;
        s[rr * 2 + 1] = acc[rr] * av2;
    }
#pragma unroll
    for (int o = 16; o > 0; o >>= 1)
#pragma unroll
        for (int i = 0; i < 8; i++)
            s[i] += __shfl_down_sync(0xFFFFFFFFu, s[i], o);
    int w = t >> 5, l = t & 31;
    if (l == 0)
#pragma unroll
        for (int i = 0; i < 8; i++) red[w][i] = s[i];
    __syncthreads();
    if (t < 16) {
        int rho = t >> 1, which = t & 1;
        int rg2 = rho >> 2, rr = rho & 3;
        float v = red[rg2 * 4 + 0][rr * 2 + which] + red[rg2 * 4 + 1][rr * 2 + which]
                + red[rg2 * 4 + 2][rr * 2 + which] + red[rg2 * 4 + 3][rr * 2 + which];
        int r = r0 + rho;
        if (which == 0) { g_Es[r]   = expf(v); g_Es2[r]   = expf(0.2f * v); }
        else            { g_Etgt[r] = expf(v); g_Etgt2[r] = expf(0.2f * v); }
    }
}

// ---------------- Kbits: bitmask + denominators (flat, schedulable loads) ---
__global__ void __launch_bounds__(256) k_bits(const int* __restrict__ adj) {
    int t = threadIdx.x;
    int l = t & 31;
    int r = blockIdx.x * 8 + (t >> 5);
    float Es = g_Es[r], Es2 = g_Es2[r];
    const int4* __restrict__ arow = (const int4*)(adj + (size_t)r * KN);
    uint32_t* __restrict__ brow = g_bits + (size_t)r * NWORDS;
    const int sh = (l & 7) * 4;
    float ls0 = 0.f, ls1 = 0.f, ls2 = 0.f, ls3 = 0.f;

#pragma unroll 8
    for (int it = 0; it < KN / 128; it++) {     // 96 iterations, 128 j per warp
        int j = it * 128 + l * 4;
        int4 m = __ldcs(arow + it * 32 + l);
        float4 e1 = *(const float4*)(g_Etgt + j);
        float4 e2 = *(const float4*)(g_Etgt2 + j);
        uint32_t nib = 0;
        if (m.x) { nib |= 1u; ls0 += fmaxf(Es * e1.x, Es2 * e2.x); }
        if (m.y) { nib |= 2u; ls1 += fmaxf(Es * e1.y, Es2 * e2.y); }
        if (m.z) { nib |= 4u; ls2 += fmaxf(Es * e1.z, Es2 * e2.z); }
        if (m.w) { nib |= 8u; ls3 += fmaxf(Es * e1.w, Es2 * e2.w); }
        uint32_t word = nib << sh;
        word |= __shfl_xor_sync(0xFFFFFFFFu, word, 1);
        word |= __shfl_xor_sync(0xFFFFFFFFu, word, 2);
        word |= __shfl_xor_sync(0xFFFFFFFFu, word, 4);
        if ((l & 7) == 0) brow[it * 4 + (l >> 3)] = word;
    }
    float lsum = (ls0 + ls1) + (ls2 + ls3);
#pragma unroll
    for (int o = 16; o > 0; o >>= 1) lsum += __shfl_down_sync(0xFFFFFFFFu, lsum, o);
    if (l == 0) {
        float inv = 1.0f / lsum;
        g_A[r] = Es * inv;
        g_B[r] = Es2 * inv;
    }
}

// ---------------- K2: fused P-gen + mma.sync GEMM (kk-pipelined) --------
#define ROWSTRIDE 272
#define VERBYTES  (128 * ROWSTRIDE)   // 34816
#define SMEM_MAIN (2 * VERBYTES)      // 69632

#define GEN_KK(JLOC, WORD0, WORD1, DST) do {                                  \
    const int j_ = jbase + (JLOC) + 4 * tq;                                   \
    float4 e1 = *(const float4*)(g_Etgt  + j_);                               \
    float4 e2 = *(const float4*)(g_Etgt2 + j_);                               \
    const uint32_t nib0 = (WORD0) >> (4 * tq);                                \
    const uint32_t nib1 = (WORD1) >> (4 * tq);                                \
    float p00 = nib0 & 1 ? fmaxf(aA0 * e1.x, bB0 * e2.x) : 0.f;               \
    float p01 = nib0 & 2 ? fmaxf(aA0 * e1.y, bB0 * e2.y) : 0.f;               \
    float p02 = nib0 & 4 ? fmaxf(aA0 * e1.z, bB0 * e2.z) : 0.f;               \
    float p03 = nib0 & 8 ? fmaxf(aA0 * e1.w, bB0 * e2.w) : 0.f;               \
    float p10 = nib1 & 1 ? fmaxf(aA1 * e1.x, bB1 * e2.x) : 0.f;               \
    float p11 = nib1 & 2 ? fmaxf(aA1 * e1.y, bB1 * e2.y) : 0.f;               \
    float p12 = nib1 & 4 ? fmaxf(aA1 * e1.z, bB1 * e2.z) : 0.f;               \
    float p13 = nib1 & 8 ? fmaxf(aA1 * e1.w, bB1 * e2.w) : 0.f;               \
    stcs4(attn0 + j_, p00, p01, p02, p03);                                    \
    stcs4(attn1 + j_, p10, p11, p12, p13);                                    \
    (DST)[0] = packh2(p00, p01);                                              \
    (DST)[1] = packh2(p10, p11);                                              \
    (DST)[2] = packh2(p02, p03);                                              \
    (DST)[3] = packh2(p12, p13);                                              \
} while (0)

__global__ void __launch_bounds__(256, 2) k_main(float* __restrict__ out) {
    extern __shared__ char sm[];
    const uint32_t smb = smem_u32(sm);
    const int t  = threadIdx.x;
    const int w  = t >> 5, l = t & 31;
    const int g  = l >> 2, tq = l & 3;
    const int ti = blockIdx.x / NSPLIT;     // row tile
    const int js = blockIdx.x % NSPLIT;     // j third
    const int i0 = ti * 128;
    const int jbase = js * JSPAN;
    const int row0 = i0 + w * 16 + g;       // warp owns 16 rows
    const int row1 = row0 + 8;

    const float aA0 = g_A[row0], bB0 = g_B[row0];
    const float aA1 = g_A[row1], bB1 = g_B[row1];
    float* __restrict__ attn0 = out + (size_t)KN * OUTF + (size_t)row0 * KN;
    float* __restrict__ attn1 = out + (size_t)KN * OUTF + (size_t)row1 * KN;
    const uint32_t* __restrict__ bw0 = g_bits + (size_t)row0 * NWORDS + js * NCL * 4;
    const uint32_t* __restrict__ bw1 = g_bits + (size_t)row1 * NWORDS + js * NCL * 4;

    const int cpr = t >> 4;          // 0..15
    const int cpk = t & 15;
    const uint32_t lmrow = ((l >> 4) & 1) * 8 + (l & 7);
    const uint32_t lmoff = lmrow * ROWSTRIDE + ((l >> 3) & 1) * 16;

    float4 acc[16];
#pragma unroll
    for (int i = 0; i < 16; i++) acc[i] = make_float4(0.f, 0.f, 0.f, 0.f);

    // prologue: chunk 0 -> buf 0
#pragma unroll
    for (int i = 0; i < 8; i++) {
        int row = cpr + i * 16;
        CP16(smb + row * ROWSTRIDE + cpk * 16,
             g_htT + (size_t)row * KN + jbase + cpk * 8);
    }
    CP_COMMIT();

    // prologue: generate fragments for (chunk 0, kk 0)
    uint32_t ahP[2][4];
    {
        const uint32_t x0 = bw0[0], x1 = bw1[0];
        GEN_KK(0, x0, x1, ahP[0]);
    }

    for (int c = 0; c < NCL; c++) {
        const int buf = c & 1;
        const uint4 w0 = *(const uint4*)(bw0 + c * 4);
        const uint4 w1 = *(const uint4*)(bw1 + c * 4);
        const int more = (c + 1 < NCL);
        const uint32_t nx0 = more ? bw0[(c + 1) * 4] : 0u;
        const uint32_t nx1 = more ? bw1[(c + 1) * 4] : 0u;

        if (more) {
            const int jn = jbase + (c + 1) * CH;
            const uint32_t dstb = smb + (buf ^ 1) * VERBYTES;
#pragma unroll
            for (int i = 0; i < 8; i++) {
                int row = cpr + i * 16;
                CP16(dstb + row * ROWSTRIDE + cpk * 16,
                     g_htT + (size_t)row * KN + jn + cpk * 8);
            }
            CP_COMMIT();
            CP_WAIT1();
        } else {
            CP_WAIT0();
        }
        __syncthreads();

        const uint32_t lmb = smb + buf * VERBYTES + lmoff;
        uint32_t b0, b1, b2, b3;
        LDMX4(b0, b1, b2, b3, lmb);        // (kk=0, np=0)
#pragma unroll
        for (int it = 0; it < 64; it++) {
            const int kk = it >> 3, np = it & 7;
            uint32_t n0, n1, n2, n3;
            if (it < 63) {
                const int itn = it + 1;
                LDMX4(n0, n1, n2, n3,
                      lmb + (itn & 7) * (16 * ROWSTRIDE) + (itn >> 3) * 32);
            }
            MMA16816(acc[2 * np],     ahP[kk & 1][0], ahP[kk & 1][1],
                                      ahP[kk & 1][2], ahP[kk & 1][3], b0, b1);
            MMA16816(acc[2 * np + 1], ahP[kk & 1][0], ahP[kk & 1][1],
                                      ahP[kk & 1][2], ahP[kk & 1][3], b2, b3);
            // interleaved fragment-gen for kk+1 (or next chunk's kk0)
            if (np == 2) {
                if (kk < 7) {
                    const uint32_t x0 = ((const uint32_t*)&w0)[(kk + 1) >> 1] >> (((kk + 1) & 1) * 16);
                    const uint32_t x1 = ((const uint32_t*)&w1)[(kk + 1) >> 1] >> (((kk + 1) & 1) * 16);
                    GEN_KK(c * CH + (kk + 1) * 16, x0, x1, ahP[(kk + 1) & 1]);
                } else if (more) {
                    GEN_KK((c + 1) * CH, nx0, nx1, ahP[0]);
                }
            }
            if (it < 63) { b0 = n0; b1 = n1; b2 = n2; b3 = n3; }
        }
        __syncthreads();
    }

    // epilogue: h_prime partial for this j-third
    float* __restrict__ part = g_part + (size_t)js * KN * OUTF;
#pragma unroll
    for (int nt = 0; nt < 16; nt++) {
        int cc = nt * 8 + 2 * tq;
        *(float2*)(part + (size_t)row0 * OUTF + cc) = make_float2(acc[nt].x, acc[nt].y);
        *(float2*)(part + (size_t)row1 * OUTF + cc) = make_float2(acc[nt].z, acc[nt].w);
    }
}

// ---------------- K3: reduce partials ----------------
__global__ void __launch_bounds__(256) k_red(float* __restrict__ out) {
    const size_t SZ = (size_t)KN * OUTF;
    size_t idx = ((size_t)blockIdx.x * 256 + threadIdx.x) * 4;
    float4 a = *(const float4*)(g_part + idx);
    float4 b = *(const float4*)(g_part + SZ + idx);
    float4 c = *(const float4*)(g_part + 2 * SZ + idx);
    *(float4*)(out + idx) = make_float4(a.x + b.x + c.x, a.y + b.y + c.y,
                                        a.z + b.z + c.z, a.w + b.w + c.w);
}

extern "C" void kernel_launch(void* const* d_in, const int* in_sizes, int n_in,
                              void* d_out, int out_size) {
    const float* h   = (const float*)d_in[0];
    const int*   adj = (const int*)d_in[1];
    const float* W   = (const float*)d_in[2];
    const float* a   = (const float*)d_in[3];
    float* out = (float*)d_out;

    cudaFuncSetAttribute(k_main, cudaFuncAttributeMaxDynamicSharedMemorySize, SMEM_MAIN);

    k_pre<<<KN / 8, 256>>>(h, W, a);
    k_bits<<<KN / 8, 256>>>(adj);
    k_main<<<(KN / 128) * NSPLIT, 256, SMEM_MAIN>>>(out);
    k_red<<<(KN * OUTF) / (256 * 4), 256>>>(out);
}